// round 7
// baseline (speedup 1.0000x reference)
#include <cuda_runtime.h>
#include <cuda_bf16.h>

#define NN      4096
#define NIN     64
#define NHID    32
#define NOUT    64
#define NHEADS  8
#define H_SP    6
#define D_INT   32
#define CAP     256
#define ALPHA   0.2f

// ---------------- scratch ----------------
__device__ int   g_deg[NN];
__device__ int   g_nbr[NN * CAP];
__device__ float g_Wh[NHEADS * NN * NHID];   // [h][n][32]
__device__ float g_f1[NHEADS * NN];          // [h][n]
__device__ float g_f2p[NN * NHEADS];         // [n][8]
__device__ float g_h[NN * (NHEADS * NHID)];  // [n][256]
__device__ float g_Who[NN * NOUT];           // [n][64]
__device__ float g_o1[NN];
__device__ float g_o2[NN];

__device__ __forceinline__ float warp_max(float v) {
    #pragma unroll
    for (int o = 16; o; o >>= 1) v = fmaxf(v, __shfl_xor_sync(0xffffffffu, v, o));
    return v;
}
__device__ __forceinline__ float warp_sum(float v) {
    #pragma unroll
    for (int o = 16; o; o >>= 1) v += __shfl_xor_sync(0xffffffffu, v, o);
    return v;
}
__device__ __forceinline__ float lrelu(float s) { return s > 0.f ? s : ALPHA * s; }

// ---------------- 1: neighbor lists (warp/row, MLP=4) ----------------
__global__ void k_build(const float* __restrict__ adj) {
    int row  = blockIdx.x * (blockDim.x >> 5) + (threadIdx.x >> 5);
    int lane = threadIdx.x & 31;
    const float4* r = reinterpret_cast<const float4*>(adj + (size_t)row * NN);
    int count = 0;
    int* nb = g_nbr + row * CAP;
    unsigned lmask = (1u << lane) - 1u;
    #pragma unroll 1
    for (int it = 0; it < 8; it++) {
        float4 v[4];
        #pragma unroll
        for (int q = 0; q < 4; q++) v[q] = r[it * 128 + q * 32 + lane];
        #pragma unroll
        for (int q = 0; q < 4; q++) {
            int base = it * 512 + q * 128 + lane * 4;
            float vals[4] = {v[q].x, v[q].y, v[q].z, v[q].w};
            #pragma unroll
            for (int e = 0; e < 4; e++) {
                bool p = vals[e] > 0.f;
                unsigned m = __ballot_sync(0xffffffffu, p);
                int pos = count + __popc(m & lmask);
                if (p && pos < CAP) nb[pos] = base + e;
                count += __popc(m);
            }
        }
    }
    if (lane == 0) g_deg[row] = count < CAP ? count : CAP;
}

// ---------------- 2: projections + attention scalars ----------------
__global__ void k_proj(const float* __restrict__ x,
                       const float* __restrict__ ie,
                       const float* __restrict__ W_sp, const float* __restrict__ a_sp,
                       const float* __restrict__ W_int, const float* __restrict__ a_int) {
    int h    = blockIdx.y;
    int r0   = blockIdx.x * 8;
    int lane = threadIdx.x;
    int rr   = threadIdx.y;
    int tid  = rr * 32 + lane;
    __shared__ float sW[NIN * NHID];
    __shared__ float sx[8 * NIN];
    __shared__ float sa[64];
    const float* W = (h < H_SP) ? (W_sp + (size_t)h * NIN * NHID)
                                : (W_int + (size_t)(h - H_SP) * NIN * NHID);
    for (int i = tid; i < NIN * NHID; i += 256) sW[i] = W[i];
    for (int i = tid; i < 8 * NIN;    i += 256) sx[i] = x[(size_t)r0 * NIN + i];
    if (tid < 64) sa[tid] = (h < H_SP) ? a_sp[h * 64 + tid] : a_int[(h - H_SP) * 64 + tid];
    __syncthreads();

    int row = r0 + rr;
    float acc = 0.f;
    #pragma unroll
    for (int k = 0; k < NIN; k++) acc = fmaf(sx[rr * NIN + k], sW[k * NHID + lane], acc);
    g_Wh[((size_t)h * NN + row) * NHID + lane] = acc;

    float p1, p2;
    if (h < H_SP) {
        p1 = acc * sa[lane];
        p2 = acc * sa[32 + lane];
    } else {
        float iv = ie[(size_t)row * D_INT + lane];
        p1 = iv * sa[lane];
        p2 = iv * sa[32 + lane];
    }
    p1 = warp_sum(p1);
    p2 = warp_sum(p2);
    if (lane == 0) { g_f1[h * NN + row] = p1; g_f2p[row * NHEADS + h] = p2; }
}

// ---------------- 3: sparse softmax + aggregate + elu (block/row) ----------------
__global__ void k_att() {
    __shared__ int   snb[CAP];
    __shared__ float sw[NHEADS][CAP];
    __shared__ float sf1[NHEADS];
    int row = blockIdx.x;
    int tid = threadIdx.x;
    int deg = g_deg[row];
    if (tid < NHEADS) sf1[tid] = g_f1[tid * NN + row];
    for (int t = tid; t < deg; t += 256) snb[t] = g_nbr[row * CAP + t];
    __syncthreads();
    for (int t = tid; t < deg; t += 256) {
        int j = snb[t];
        float4 a = *reinterpret_cast<const float4*>(&g_f2p[(size_t)j * 8]);
        float4 b = *reinterpret_cast<const float4*>(&g_f2p[(size_t)j * 8 + 4]);
        sw[0][t] = lrelu(sf1[0] + a.x);  sw[1][t] = lrelu(sf1[1] + a.y);
        sw[2][t] = lrelu(sf1[2] + a.z);  sw[3][t] = lrelu(sf1[3] + a.w);
        sw[4][t] = lrelu(sf1[4] + b.x);  sw[5][t] = lrelu(sf1[5] + b.y);
        sw[6][t] = lrelu(sf1[6] + b.z);  sw[7][t] = lrelu(sf1[7] + b.w);
    }
    __syncthreads();

    int h = tid >> 5, lane = tid & 31;
    float mx = -1e30f;
    for (int t = lane; t < deg; t += 32) mx = fmaxf(mx, sw[h][t]);
    mx = warp_max(mx);
    float sm = 0.f;
    for (int t = lane; t < deg; t += 32) {
        float e = __expf(sw[h][t] - mx);
        sw[h][t] = e;
        sm += e;
    }
    sm = warp_sum(sm);
    __syncwarp();
    float inv = 1.f / sm;

    const float* Wh = g_Wh + (size_t)h * NN * NHID;
    float acc = 0.f;
    #pragma unroll 4
    for (int t = 0; t < deg; t++) {
        int j = snb[t];
        acc = fmaf(sw[h][t] * inv, Wh[(size_t)j * NHID + lane], acc);
    }
    acc = acc > 0.f ? acc : (__expf(acc) - 1.f);
    g_h[(size_t)row * 256 + h * NHID + lane] = acc;
}

// ---------------- 4: Who = h @ W_out (smem-staged, transposed h), fused o1/o2 ----------------
#define WHO_ROWS 16
__global__ void k_who(const float* __restrict__ W_out, const float* __restrict__ a_out) {
    __shared__ float sht[256][WHO_ROWS];  // transposed h tile, 16KB
    __shared__ float sW[64][64];          // W_out chunk, 16KB
    __shared__ float sp1[8][4], sp2[8][4];
    int r0   = blockIdx.x * WHO_ROWS;
    int tid  = threadIdx.x;
    int c    = tid & 63;
    int rg   = tid >> 6;          // 0..3 -> rows rg*4..rg*4+3
    int w    = tid >> 5;
    int lane = tid & 31;

    // load h tile transposed: sht[k][r] = g_h[(r0+r)*256 + k]
    for (int i = tid; i < WHO_ROWS * 256; i += 256) {
        int r = i >> 8, k = i & 255;
        sht[k][r] = g_h[(size_t)(r0 + r) * 256 + k];
    }

    float acc[4] = {0.f, 0.f, 0.f, 0.f};
    #pragma unroll 1
    for (int kc = 0; kc < 4; kc++) {
        __syncthreads();
        for (int i = tid; i < 64 * 64; i += 256)
            sW[i >> 6][i & 63] = W_out[(size_t)(kc * 64 + (i >> 6)) * 64 + (i & 63)];
        __syncthreads();
        #pragma unroll 8
        for (int k = 0; k < 64; k++) {
            float wv = sW[k][c];
            float4 hv = *reinterpret_cast<const float4*>(&sht[kc * 64 + k][rg * 4]);
            acc[0] = fmaf(hv.x, wv, acc[0]);
            acc[1] = fmaf(hv.y, wv, acc[1]);
            acc[2] = fmaf(hv.z, wv, acc[2]);
            acc[3] = fmaf(hv.w, wv, acc[3]);
        }
    }

    float a1 = __ldg(&a_out[c]), a2 = __ldg(&a_out[64 + c]);
    #pragma unroll
    for (int i = 0; i < 4; i++) {
        g_Who[(size_t)(r0 + rg * 4 + i) * 64 + c] = acc[i];
        float p1 = warp_sum(acc[i] * a1);
        float p2 = warp_sum(acc[i] * a2);
        if (lane == 0) { sp1[w][i] = p1; sp2[w][i] = p2; }
    }
    __syncthreads();
    if (tid < WHO_ROWS) {
        int rgf = tid >> 2, i = tid & 3;
        g_o1[r0 + tid] = sp1[rgf * 2][i] + sp1[rgf * 2 + 1][i];
        g_o2[r0 + tid] = sp2[rgf * 2][i] + sp2[rgf * 2 + 1][i];
    }
}

// ---------------- 5: output attention + tanh (block/row) ----------------
__global__ void k_out(float* __restrict__ out) {
    __shared__ int   snb[CAP];
    __shared__ float sw[CAP];
    __shared__ float sred[8];
    __shared__ float sp[4][64];
    int row = blockIdx.x;
    int tid = threadIdx.x;
    int deg = g_deg[row];
    for (int t = tid; t < deg; t += 256) snb[t] = g_nbr[row * CAP + t];
    __syncthreads();
    float o1r = g_o1[row];
    float lm = -1e30f;
    for (int t = tid; t < deg; t += 256) {
        float s = lrelu(o1r + g_o2[snb[t]]);
        sw[t] = s;
        lm = fmaxf(lm, s);
    }
    lm = warp_max(lm);
    if ((tid & 31) == 0) sred[tid >> 5] = lm;
    __syncthreads();
    float mx = fmaxf(fmaxf(fmaxf(sred[0], sred[1]), fmaxf(sred[2], sred[3])),
                     fmaxf(fmaxf(sred[4], sred[5]), fmaxf(sred[6], sred[7])));
    __syncthreads();
    float ls = 0.f;
    for (int t = tid; t < deg; t += 256) {
        float e = __expf(sw[t] - mx);
        sw[t] = e;
        ls += e;
    }
    ls = warp_sum(ls);
    if ((tid & 31) == 0) sred[tid >> 5] = ls;
    __syncthreads();
    float inv = 1.f / (sred[0] + sred[1] + sred[2] + sred[3] +
                       sred[4] + sred[5] + sred[6] + sred[7]);

    int w = tid >> 5, lane = tid & 31;
    int chunk = w >> 1;
    int d = (w & 1) * 32 + lane;
    float acc = 0.f;
    #pragma unroll 4
    for (int t = chunk; t < deg; t += 4)
        acc = fmaf(sw[t] * inv, g_Who[(size_t)snb[t] * 64 + d], acc);
    sp[chunk][d] = acc;
    __syncthreads();
    if (tid < 64)
        out[(size_t)row * 64 + tid] =
            tanhf(sp[0][tid] + sp[1][tid] + sp[2][tid] + sp[3][tid]);
}

// ---------------- launch ----------------
extern "C" void kernel_launch(void* const* d_in, const int* in_sizes, int n_in,
                              void* d_out, int out_size) {
    const float* x     = (const float*)d_in[0];
    const float* adj   = (const float*)d_in[1];
    const float* ie    = (const float*)d_in[2];
    const float* W_sp  = (const float*)d_in[3];
    const float* a_sp  = (const float*)d_in[4];
    const float* W_int = (const float*)d_in[5];
    const float* a_int = (const float*)d_in[6];
    const float* W_out = (const float*)d_in[7];
    const float* a_out = (const float*)d_in[8];
    float* out = (float*)d_out;

    k_build<<<NN / 8, 256>>>(adj);
    k_proj<<<dim3(NN / 8, NHEADS), dim3(32, 8)>>>(x, ie, W_sp, a_sp, W_int, a_int);
    k_att<<<NN, 256>>>();
    k_who<<<NN / WHO_ROWS, 256>>>(W_out, a_out);
    k_out<<<NN, 256>>>(out);
}

// round 9
// speedup vs baseline: 1.0968x; 1.0968x over previous
#include <cuda_runtime.h>
#include <cuda_bf16.h>

#define NN      4096
#define NIN     64
#define NHID    32
#define NOUT    64
#define NHEADS  8
#define H_SP    6
#define D_INT   32
#define CAP     256
#define ALPHA   0.2f

// ---------------- scratch ----------------
__device__ int   g_deg[NN];
__device__ int   g_nbr[NN * CAP];
__device__ float g_Wh[NHEADS * NN * NHID];   // [h][n][32]
__device__ float g_f1[NHEADS * NN];          // [h][n]
__device__ float g_f2p[NN * NHEADS];         // [n][8]
__device__ float g_h[NN * (NHEADS * NHID)];  // [n][256]
__device__ float g_Who[NN * NOUT];           // [n][64]
__device__ float g_o1[NN];
__device__ float g_o2[NN];

__device__ __forceinline__ float warp_max(float v) {
    #pragma unroll
    for (int o = 16; o; o >>= 1) v = fmaxf(v, __shfl_xor_sync(0xffffffffu, v, o));
    return v;
}
__device__ __forceinline__ float warp_sum(float v) {
    #pragma unroll
    for (int o = 16; o; o >>= 1) v += __shfl_xor_sync(0xffffffffu, v, o);
    return v;
}
__device__ __forceinline__ float lrelu(float s) { return s > 0.f ? s : ALPHA * s; }

// ---------------- 1: neighbor lists (warp/row, MLP=4) ----------------
__global__ void k_build(const float* __restrict__ adj) {
    int row  = blockIdx.x * (blockDim.x >> 5) + (threadIdx.x >> 5);
    int lane = threadIdx.x & 31;
    const float4* r = reinterpret_cast<const float4*>(adj + (size_t)row * NN);
    int count = 0;
    int* nb = g_nbr + row * CAP;
    unsigned lmask = (1u << lane) - 1u;
    #pragma unroll 1
    for (int it = 0; it < 8; it++) {
        float4 v[4];
        #pragma unroll
        for (int q = 0; q < 4; q++) v[q] = r[it * 128 + q * 32 + lane];
        #pragma unroll
        for (int q = 0; q < 4; q++) {
            int base = it * 512 + q * 128 + lane * 4;
            float vals[4] = {v[q].x, v[q].y, v[q].z, v[q].w};
            #pragma unroll
            for (int e = 0; e < 4; e++) {
                bool p = vals[e] > 0.f;
                unsigned m = __ballot_sync(0xffffffffu, p);
                int pos = count + __popc(m & lmask);
                if (p && pos < CAP) nb[pos] = base + e;
                count += __popc(m);
            }
        }
    }
    if (lane == 0) g_deg[row] = count < CAP ? count : CAP;
}

// ---------------- 2: projections + attention scalars ----------------
__global__ void k_proj(const float* __restrict__ x,
                       const float* __restrict__ ie,
                       const float* __restrict__ W_sp, const float* __restrict__ a_sp,
                       const float* __restrict__ W_int, const float* __restrict__ a_int) {
    int h    = blockIdx.y;
    int r0   = blockIdx.x * 8;
    int lane = threadIdx.x;
    int rr   = threadIdx.y;
    int tid  = rr * 32 + lane;
    __shared__ float sW[NIN * NHID];
    __shared__ float sx[8 * NIN];
    __shared__ float sa[64];
    const float* W = (h < H_SP) ? (W_sp + (size_t)h * NIN * NHID)
                                : (W_int + (size_t)(h - H_SP) * NIN * NHID);
    for (int i = tid; i < NIN * NHID; i += 256) sW[i] = W[i];
    for (int i = tid; i < 8 * NIN;    i += 256) sx[i] = x[(size_t)r0 * NIN + i];
    if (tid < 64) sa[tid] = (h < H_SP) ? a_sp[h * 64 + tid] : a_int[(h - H_SP) * 64 + tid];
    __syncthreads();

    int row = r0 + rr;
    float acc = 0.f;
    #pragma unroll
    for (int k = 0; k < NIN; k++) acc = fmaf(sx[rr * NIN + k], sW[k * NHID + lane], acc);
    g_Wh[((size_t)h * NN + row) * NHID + lane] = acc;

    float p1, p2;
    if (h < H_SP) {
        p1 = acc * sa[lane];
        p2 = acc * sa[32 + lane];
    } else {
        float iv = ie[(size_t)row * D_INT + lane];
        p1 = iv * sa[lane];
        p2 = iv * sa[32 + lane];
    }
    p1 = warp_sum(p1);
    p2 = warp_sum(p2);
    if (lane == 0) { g_f1[h * NN + row] = p1; g_f2p[row * NHEADS + h] = p2; }
}

// ---------------- 3: sparse softmax + aggregate + elu (block/row) ----------------
__global__ void k_att() {
    __shared__ int   snb[CAP];
    __shared__ float sw[NHEADS][CAP];
    __shared__ float sf1[NHEADS];
    int row = blockIdx.x;
    int tid = threadIdx.x;
    int deg = g_deg[row];
    if (tid < NHEADS) sf1[tid] = g_f1[tid * NN + row];
    for (int t = tid; t < deg; t += 256) snb[t] = g_nbr[row * CAP + t];
    __syncthreads();
    for (int t = tid; t < deg; t += 256) {
        int j = snb[t];
        float4 a = *reinterpret_cast<const float4*>(&g_f2p[(size_t)j * 8]);
        float4 b = *reinterpret_cast<const float4*>(&g_f2p[(size_t)j * 8 + 4]);
        sw[0][t] = lrelu(sf1[0] + a.x);  sw[1][t] = lrelu(sf1[1] + a.y);
        sw[2][t] = lrelu(sf1[2] + a.z);  sw[3][t] = lrelu(sf1[3] + a.w);
        sw[4][t] = lrelu(sf1[4] + b.x);  sw[5][t] = lrelu(sf1[5] + b.y);
        sw[6][t] = lrelu(sf1[6] + b.z);  sw[7][t] = lrelu(sf1[7] + b.w);
    }
    __syncthreads();

    int h = tid >> 5, lane = tid & 31;
    float mx = -1e30f;
    for (int t = lane; t < deg; t += 32) mx = fmaxf(mx, sw[h][t]);
    mx = warp_max(mx);
    float sm = 0.f;
    for (int t = lane; t < deg; t += 32) {
        float e = __expf(sw[h][t] - mx);
        sw[h][t] = e;
        sm += e;
    }
    sm = warp_sum(sm);
    __syncwarp();
    float inv = 1.f / sm;

    const float* Wh = g_Wh + (size_t)h * NN * NHID;
    float acc = 0.f;
    for (int t = 0; t < deg; t++) {
        int j = snb[t];
        acc = fmaf(sw[h][t] * inv, Wh[(size_t)j * NHID + lane], acc);
    }
    acc = acc > 0.f ? acc : (__expf(acc) - 1.f);
    g_h[(size_t)row * 256 + h * NHID + lane] = acc;
}

// ---------------- 4: Who = h @ W_out (8 rows/block, grid 512), fused o1/o2 ----------------
#define WHO_ROWS 8
#define SHT_PAD 10
__global__ void k_who(const float* __restrict__ W_out, const float* __restrict__ a_out) {
    __shared__ float sht[256][SHT_PAD];   // transposed h tile (8 rows, padded), 10KB
    __shared__ float sW[64][64];          // W_out chunk, 16KB
    __shared__ float sp1[8][2], sp2[8][2];
    int r0   = blockIdx.x * WHO_ROWS;
    int tid  = threadIdx.x;
    int c    = tid & 63;
    int rg   = tid >> 6;          // 0..3 -> rows rg*2, rg*2+1
    int w    = tid >> 5;
    int lane = tid & 31;

    // load h tile transposed: sht[k][r] = g_h[(r0+r)*256 + k]
    for (int i = tid; i < WHO_ROWS * 256; i += 256) {
        int r = i >> 8, k = i & 255;
        sht[k][r] = g_h[(size_t)(r0 + r) * 256 + k];
    }

    float acc0 = 0.f, acc1 = 0.f;
    #pragma unroll 1
    for (int kc = 0; kc < 4; kc++) {
        __syncthreads();
        for (int i = tid; i < 64 * 64; i += 256)
            sW[i >> 6][i & 63] = W_out[(size_t)(kc * 64 + (i >> 6)) * 64 + (i & 63)];
        __syncthreads();
        #pragma unroll 8
        for (int k = 0; k < 64; k++) {
            float wv = sW[k][c];
            float2 hv = *reinterpret_cast<const float2*>(&sht[kc * 64 + k][rg * 2]);
            acc0 = fmaf(hv.x, wv, acc0);
            acc1 = fmaf(hv.y, wv, acc1);
        }
    }

    float a1 = __ldg(&a_out[c]), a2 = __ldg(&a_out[64 + c]);
    g_Who[(size_t)(r0 + rg * 2 + 0) * 64 + c] = acc0;
    g_Who[(size_t)(r0 + rg * 2 + 1) * 64 + c] = acc1;
    float p10 = warp_sum(acc0 * a1), p20 = warp_sum(acc0 * a2);
    float p11 = warp_sum(acc1 * a1), p21 = warp_sum(acc1 * a2);
    if (lane == 0) {
        sp1[w][0] = p10; sp2[w][0] = p20;
        sp1[w][1] = p11; sp2[w][1] = p21;
    }
    __syncthreads();
    if (tid < WHO_ROWS) {
        int rgf = tid >> 1, i = tid & 1;   // row = rgf*2 + i
        g_o1[r0 + tid] = sp1[rgf * 2][i] + sp1[rgf * 2 + 1][i];
        g_o2[r0 + tid] = sp2[rgf * 2][i] + sp2[rgf * 2 + 1][i];
    }
}

// ---------------- 5: output attention + tanh (block/row) ----------------
__global__ void k_out(float* __restrict__ out) {
    __shared__ int   snb[CAP];
    __shared__ float sw[CAP];
    __shared__ float sred[8];
    __shared__ float sp[4][64];
    int row = blockIdx.x;
    int tid = threadIdx.x;
    int deg = g_deg[row];
    for (int t = tid; t < deg; t += 256) snb[t] = g_nbr[row * CAP + t];
    __syncthreads();
    float o1r = g_o1[row];
    float lm = -1e30f;
    for (int t = tid; t < deg; t += 256) {
        float s = lrelu(o1r + g_o2[snb[t]]);
        sw[t] = s;
        lm = fmaxf(lm, s);
    }
    lm = warp_max(lm);
    if ((tid & 31) == 0) sred[tid >> 5] = lm;
    __syncthreads();
    float mx = fmaxf(fmaxf(fmaxf(sred[0], sred[1]), fmaxf(sred[2], sred[3])),
                     fmaxf(fmaxf(sred[4], sred[5]), fmaxf(sred[6], sred[7])));
    __syncthreads();
    float ls = 0.f;
    for (int t = tid; t < deg; t += 256) {
        float e = __expf(sw[t] - mx);
        sw[t] = e;
        ls += e;
    }
    ls = warp_sum(ls);
    if ((tid & 31) == 0) sred[tid >> 5] = ls;
    __syncthreads();
    float inv = 1.f / (sred[0] + sred[1] + sred[2] + sred[3] +
                       sred[4] + sred[5] + sred[6] + sred[7]);

    int w = tid >> 5, lane = tid & 31;
    int chunk = w >> 1;
    int d = (w & 1) * 32 + lane;
    float acc = 0.f;
    for (int t = chunk; t < deg; t += 4)
        acc = fmaf(sw[t] * inv, g_Who[(size_t)snb[t] * 64 + d], acc);
    sp[chunk][d] = acc;
    __syncthreads();
    if (tid < 64)
        out[(size_t)row * 64 + tid] =
            tanhf(sp[0][tid] + sp[1][tid] + sp[2][tid] + sp[3][tid]);
}

// ---------------- launch ----------------
extern "C" void kernel_launch(void* const* d_in, const int* in_sizes, int n_in,
                              void* d_out, int out_size) {
    const float* x     = (const float*)d_in[0];
    const float* adj   = (const float*)d_in[1];
    const float* ie    = (const float*)d_in[2];
    const float* W_sp  = (const float*)d_in[3];
    const float* a_sp  = (const float*)d_in[4];
    const float* W_int = (const float*)d_in[5];
    const float* a_int = (const float*)d_in[6];
    const float* W_out = (const float*)d_in[7];
    const float* a_out = (const float*)d_in[8];
    float* out = (float*)d_out;

    k_build<<<NN / 8, 256>>>(adj);
    k_proj<<<dim3(NN / 8, NHEADS), dim3(32, 8)>>>(x, ie, W_sp, a_sp, W_int, a_int);
    k_att<<<NN, 256>>>();
    k_who<<<NN / WHO_ROWS, 256>>>(W_out, a_out);
    k_out<<<NN, 256>>>(out);
}